// round 1
// baseline (speedup 1.0000x reference)
#include <cuda_runtime.h>

// Problem constants (fixed by the dataset)
#define BB 16
#define TT 4096
#define DD 512
#define NROWS (BB*TT)   // 65536

// PAD=10, BOS=11, EOS=12, ROW=13, SEP=14; digits 0..9

// Scratch (device globals — no allocations allowed)
__device__ unsigned char g_rc[NROWS * 2];     // packed (r, c) per position, clipped emits
__device__ float g_srow[30 * DD];             // srow[r][e]
__device__ float g_scol[30 * DD];             // scol[c][e]

struct Summ {
    int g0, g1;           // grid_out for grid_in = 0 / 1
    int rConst, rVal;     // row: const (rVal) or delta (row_in + rVal)
    int c0Const, c1Const; // col const-vs-delta per grid_in branch
    int c0, c1;
};

// ---------------------------------------------------------------------------
// Kernel 1: 2D-id scan. One block per batch sequence, 128 threads, 32 tokens
// per thread chunk. Pass A: per-chunk transition summaries (both in_grid
// branches). Serial combine by thread 0 (128 steps). Pass B: replay + emit.
// ---------------------------------------------------------------------------
__global__ void __launch_bounds__(128) scan_kernel(const int* __restrict__ ids) {
    __shared__ Summ ssum[128];
    __shared__ int sg[128], sr[128], sc[128];

    const int b = blockIdx.x;
    const int tid = threadIdx.x;
    const int* base = ids + b * TT + tid * 32;

    // ---- Pass A: chunk summary ----
    int g0 = 0, g1 = 1;
    int rConst = 0, rVal = 0;
    int c0Const = 0, c1Const = 0, c0 = 0, c1 = 0;
    #pragma unroll 8
    for (int j = 0; j < 32; j++) {
        int tok = base[j];
        int bos = (tok == 11), sep = (tok == 14), rw = (tok == 13);
        int end = (tok == 12) | (tok == 10);
        int dig = (tok <= 9);
        // row (grid-independent)
        if (bos | sep) { rConst = 1; rVal = 0; }
        else if (rw) rVal++;
        // col, branch grid_in = 0
        {
            int gc = g0 & dig;
            if (bos | sep | rw) { c0Const = 1; c0 = 0; }
            else if (gc) c0++;
            g0 = bos ? 1 : (end ? 0 : g0);
        }
        // col, branch grid_in = 1
        {
            int gc = g1 & dig;
            if (bos | sep | rw) { c1Const = 1; c1 = 0; }
            else if (gc) c1++;
            g1 = bos ? 1 : (end ? 0 : g1);
        }
    }
    ssum[tid].g0 = g0;  ssum[tid].g1 = g1;
    ssum[tid].rConst = rConst; ssum[tid].rVal = rVal;
    ssum[tid].c0Const = c0Const; ssum[tid].c1Const = c1Const;
    ssum[tid].c0 = c0; ssum[tid].c1 = c1;
    __syncthreads();

    // ---- Serial combine: entry state per chunk ----
    if (tid == 0) {
        int g = 0, r = 0, c = 0;
        for (int i = 0; i < 128; i++) {
            sg[i] = g; sr[i] = r; sc[i] = c;
            Summ s = ssum[i];
            int nr = s.rConst ? s.rVal : r + s.rVal;
            int nc, ng;
            if (g) { nc = s.c1Const ? s.c1 : c + s.c1; ng = s.g1; }
            else   { nc = s.c0Const ? s.c0 : c + s.c0; ng = s.g0; }
            g = ng; r = nr; c = nc;
        }
    }
    __syncthreads();

    // ---- Pass B: replay with true entry state, emit clipped (r, c) ----
    int g = sg[tid], r = sr[tid], c = sc[tid];
    unsigned int buf[16];
    #pragma unroll
    for (int j = 0; j < 32; j++) {
        int tok = base[j];
        int bos = (tok == 11), sep = (tok == 14), rw = (tok == 13);
        int end = (tok == 12) | (tok == 10);
        int dig = (tok <= 9);
        int gc = g & dig;
        unsigned int er = gc ? (unsigned)min(r, 29) : 0u;
        unsigned int ec = gc ? (unsigned)min(c, 29) : 0u;
        unsigned int pair = er | (ec << 8);
        if (j & 1) buf[j >> 1] |= (pair << 16);
        else       buf[j >> 1] = pair;
        // state update (emit uses pre-update state, per reference)
        g = bos ? 1 : (end ? 0 : g);
        r = (bos | sep) ? 0 : (rw ? r + 1 : r);
        c = (bos | sep | rw) ? 0 : (gc ? c + 1 : c);
    }
    uint4* dst = (uint4*)(g_rc + (size_t)(b * TT + tid * 32) * 2);
    const uint4* srcb = (const uint4*)buf;
    dst[0] = srcb[0]; dst[1] = srcb[1]; dst[2] = srcb[2]; dst[3] = srcb[3];
}

// ---------------------------------------------------------------------------
// Kernel 2: precompute srow[r][e], scol[c][e]. One block per output column e.
// srow[r][e] = sum_{d<256} row_table[r][d] * W[e][d]
// scol[c][e] = sum_{d<256} col_table[c][d] * W[e][256+d]
// ---------------------------------------------------------------------------
__global__ void __launch_bounds__(64) precompute_kernel(
    const float* __restrict__ row_tab,   // (30, 256)
    const float* __restrict__ col_tab,   // (30, 256)
    const float* __restrict__ W)         // (512, 512), e-major
{
    __shared__ float w[DD];
    const int e = blockIdx.x;
    for (int i = threadIdx.x; i < DD; i += 64) w[i] = W[(size_t)e * DD + i];
    __syncthreads();

    const int t = threadIdx.x;
    if (t < 30) {
        float s = 0.f;
        const float* tr = row_tab + t * 256;
        #pragma unroll 8
        for (int d = 0; d < 256; d++) s = fmaf(tr[d], w[d], s);
        g_srow[t * DD + e] = s;
    } else if (t >= 32 && t < 62) {
        const int r = t - 32;
        float s = 0.f;
        const float* tc = col_tab + r * 256;
        #pragma unroll 8
        for (int d = 0; d < 256; d++) s = fmaf(tc[d], w[256 + d], s);
        g_scol[r * DD + e] = s;
    }
}

// ---------------------------------------------------------------------------
// Kernel 3: fused gather + add + mask + LayerNorm. One warp per (b,t) row.
// ---------------------------------------------------------------------------
__global__ void __launch_bounds__(256) main_kernel(
    const int* __restrict__ ids,
    const float* __restrict__ tok_tab,   // (15, 512)
    const float* __restrict__ pos_tab,   // (4096, 512)
    const float* __restrict__ gamma,     // (512,)
    const float* __restrict__ beta,      // (512,)
    float* __restrict__ out)             // (B, T, 512)
{
    const int row = blockIdx.x * 8 + (threadIdx.x >> 5);
    const int lane = threadIdx.x & 31;
    const int t = row & (TT - 1);

    const int tok = ids[row];
    const unsigned int pr = ((const unsigned short*)g_rc)[row];
    const int r = pr & 0xff;
    const int c = (pr >> 8) & 0xff;
    const float mask = (tok <= 9) ? 1.f : 0.f;

    const float4* tp = (const float4*)(tok_tab + (size_t)tok * DD);
    const float4* pp = (const float4*)(pos_tab + (size_t)t * DD);
    const float4* rp = (const float4*)(g_srow + r * DD);
    const float4* cp = (const float4*)(g_scol + c * DD);

    float4 x[4];
    float sum = 0.f, sq = 0.f;
    #pragma unroll
    for (int i = 0; i < 4; i++) {
        const int idx = lane + i * 32;
        float4 a = tp[idx];
        float4 p = pp[idx];
        float4 rr = rp[idx];
        float4 cc = cp[idx];
        float4 v;
        v.x = fmaf(mask, rr.x + cc.x, a.x + p.x);
        v.y = fmaf(mask, rr.y + cc.y, a.y + p.y);
        v.z = fmaf(mask, rr.z + cc.z, a.z + p.z);
        v.w = fmaf(mask, rr.w + cc.w, a.w + p.w);
        x[i] = v;
        sum += (v.x + v.y) + (v.z + v.w);
        sq = fmaf(v.x, v.x, sq);
        sq = fmaf(v.y, v.y, sq);
        sq = fmaf(v.z, v.z, sq);
        sq = fmaf(v.w, v.w, sq);
    }

    #pragma unroll
    for (int o = 16; o > 0; o >>= 1) {
        sum += __shfl_xor_sync(0xffffffffu, sum, o);
        sq  += __shfl_xor_sync(0xffffffffu, sq,  o);
    }

    const float mu = sum * (1.f / (float)DD);
    const float var = sq * (1.f / (float)DD) - mu * mu;
    const float inv = rsqrtf(var + 1e-5f);

    float4* op = (float4*)(out + (size_t)row * DD);
    const float4* gp = (const float4*)gamma;
    const float4* bp = (const float4*)beta;
    #pragma unroll
    for (int i = 0; i < 4; i++) {
        const int idx = lane + i * 32;
        float4 gm = gp[idx];
        float4 bt = bp[idx];
        float4 v = x[i];
        v.x = fmaf((v.x - mu) * inv, gm.x, bt.x);
        v.y = fmaf((v.y - mu) * inv, gm.y, bt.y);
        v.z = fmaf((v.z - mu) * inv, gm.z, bt.z);
        v.w = fmaf((v.w - mu) * inv, gm.w, bt.w);
        op[idx] = v;
    }
}

// ---------------------------------------------------------------------------
// Launch
// ---------------------------------------------------------------------------
extern "C" void kernel_launch(void* const* d_in, const int* in_sizes, int n_in,
                              void* d_out, int out_size) {
    const int*   ids    = (const int*)  d_in[0];  // input_ids (16, 4096) int32
    const float* tokt   = (const float*)d_in[1];  // token_table (15, 512)
    const float* post   = (const float*)d_in[2];  // pos_table (4096, 512)
    const float* rowt   = (const float*)d_in[3];  // row_table (30, 256)
    const float* colt   = (const float*)d_in[4];  // col_table (30, 256)
    const float* W      = (const float*)d_in[5];  // w_spatial (512, 512)
    const float* gamma  = (const float*)d_in[6];  // ln_gamma (512,)
    const float* beta   = (const float*)d_in[7];  // ln_beta (512,)
    float* out = (float*)d_out;

    (void)in_sizes; (void)n_in; (void)out_size;

    scan_kernel<<<BB, 128>>>(ids);
    precompute_kernel<<<DD, 64>>>(rowt, colt, W);
    main_kernel<<<NROWS / 8, 256>>>(ids, tokt, post, gamma, beta, out);
}